// round 9
// baseline (speedup 1.0000x reference)
#include <cuda_runtime.h>
#include <math.h>
#include <stdint.h>

#define LSEQ  32768
#define CDIM  256      // projected channels
#define QDIM  512      // input/output channels
#define BLK   512      // attention block length
#define HALF  256
#define QT    64       // query tile per CTA

typedef unsigned long long u64;

// ---- packed f32x2 helpers (sm_100+; ptxas never auto-generates FFMA2) ----
__device__ __forceinline__ u64 pk2(float lo, float hi) {
    u64 r;
    asm("mov.b64 %0, {%1, %2};" : "=l"(r)
        : "r"(__float_as_uint(lo)), "r"(__float_as_uint(hi)));
    return r;
}
__device__ __forceinline__ u64 dup2(float v) { return pk2(v, v); }
__device__ __forceinline__ void fma2(u64 &d, u64 a, u64 b) {
    asm("fma.rn.f32x2 %0, %1, %2, %0;" : "+l"(d) : "l"(a), "l"(b));
}
__device__ __forceinline__ void mul2(u64 &d, u64 a) {
    asm("mul.rn.f32x2 %0, %0, %1;" : "+l"(d) : "l"(a));
}
__device__ __forceinline__ float2 up2(u64 v) {
    float2 f;
    unsigned lo, hi;
    asm("mov.b64 {%0, %1}, %2;" : "=r"(lo), "=r"(hi) : "l"(v));
    f.x = __uint_as_float(lo); f.y = __uint_as_float(hi);
    return f;
}

// ---- scratch (static device globals; runtime alloc is forbidden) ----
__device__ float g_q[(size_t)CDIM * LSEQ];
__device__ float g_k[(size_t)CDIM * LSEQ];
__device__ float g_v[(size_t)CDIM * LSEQ];
__device__ float g_att[(size_t)CDIM * LSEQ];

// ============================================================================
// GEMM: out[m][l] = bias[m] + sum_k W[m][k] * X[k][l]   (optionally * mm[l])
// Tile 128x128, BK=16, 256 threads. Microtile 16 rows x 4 cols per thread:
// row-pairs packed into f32x2 accumulators (packs free from float4 LDS),
// only the 4 column values need dup movs -> ~41 issues per 64 fma-cycles
// per warp per kk -> fma-pipe-bound. Register-prefetch of next K-tile.
// ============================================================================
__global__ __launch_bounds__(256, 2) void gemm_kernel(
    const float* __restrict__ W, const float* __restrict__ X,
    const float* __restrict__ bias, float* __restrict__ outp,
    int K, const float* __restrict__ mm)
{
    __shared__ float Ws[16][128];
    __shared__ float Xs[16][128];

    const int n0 = blockIdx.x * 128;
    const int m0 = blockIdx.y * 128;
    const int tid = threadIdx.x;
    const int tx = tid & 31;    // cols tx*4 .. +3
    const int ty = tid >> 5;    // rows ty*16 .. +15 (warp-uniform)

    // per-thread load coordinates (fixed across tiles)
    const int wm = tid >> 4,  wk = tid & 15;    // W: 8 rows, stride 16 in m
    const int xk = tid >> 7,  xn = tid & 127;   // X: 8 k-rows, stride 2 in k

    u64 acc2[8][4];             // [row-pair p][col j]: rows (ty*16+2p, +1)
#pragma unroll
    for (int i = 0; i < 8; i++)
#pragma unroll
        for (int j = 0; j < 4; j++) acc2[i][j] = 0ull;

    float wreg[8], xreg[8];

    // prefetch tile 0
#pragma unroll
    for (int i = 0; i < 8; i++)
        wreg[i] = W[(size_t)(m0 + wm + 16 * i) * K + wk];
#pragma unroll
    for (int i = 0; i < 8; i++)
        xreg[i] = X[(size_t)(xk + 2 * i) * LSEQ + n0 + xn];

    for (int k0 = 0; k0 < K; k0 += 16) {
        // commit prefetched tile to smem
#pragma unroll
        for (int i = 0; i < 8; i++) Ws[wk][wm + 16 * i] = wreg[i];
#pragma unroll
        for (int i = 0; i < 8; i++) Xs[xk + 2 * i][xn] = xreg[i];
        __syncthreads();

        // prefetch next tile while computing this one
        if (k0 + 16 < K) {
#pragma unroll
            for (int i = 0; i < 8; i++)
                wreg[i] = W[(size_t)(m0 + wm + 16 * i) * K + k0 + 16 + wk];
#pragma unroll
            for (int i = 0; i < 8; i++)
                xreg[i] = X[(size_t)(k0 + 16 + xk + 2 * i) * LSEQ + n0 + xn];
        }

#pragma unroll
        for (int kk = 0; kk < 16; kk++) {
            float4 a0 = *(const float4*)&Ws[kk][ty * 16];
            float4 a1 = *(const float4*)&Ws[kk][ty * 16 + 4];
            float4 a2 = *(const float4*)&Ws[kk][ty * 16 + 8];
            float4 a3 = *(const float4*)&Ws[kk][ty * 16 + 12];
            u64 ra[8] = {pk2(a0.x, a0.y), pk2(a0.z, a0.w),
                         pk2(a1.x, a1.y), pk2(a1.z, a1.w),
                         pk2(a2.x, a2.y), pk2(a2.z, a2.w),
                         pk2(a3.x, a3.y), pk2(a3.z, a3.w)};
            float4 b = *(const float4*)&Xs[kk][tx * 4];
            u64 rb[4] = {dup2(b.x), dup2(b.y), dup2(b.z), dup2(b.w)};
#pragma unroll
            for (int p = 0; p < 8; p++)
#pragma unroll
                for (int j = 0; j < 4; j++) fma2(acc2[p][j], ra[p], rb[j]);
        }
        __syncthreads();
    }

    // epilogue: bias, optional mask, float4 stores
    float mv[4];
#pragma unroll
    for (int j = 0; j < 4; j++)
        mv[j] = mm ? mm[n0 + tx * 4 + j] : 1.f;
#pragma unroll
    for (int p = 0; p < 8; p++) {
        int r0 = m0 + ty * 16 + 2 * p;
        int r1 = r0 + 1;
        float bb0 = bias[r0], bb1 = bias[r1];
        float v0[4], v1[4];
#pragma unroll
        for (int j = 0; j < 4; j++) {
            float2 q = up2(acc2[p][j]);
            v0[j] = (q.x + bb0) * mv[j];
            v1[j] = (q.y + bb1) * mv[j];
        }
        *(float4*)&outp[(size_t)r0 * LSEQ + n0 + tx * 4] = make_float4(v0[0], v0[1], v0[2], v0[3]);
        *(float4*)&outp[(size_t)r1 * LSEQ + n0 + tx * 4] = make_float4(v1[0], v1[1], v1[2], v1[3]);
    }
}

// ============================================================================
// Sliding-window attention with online softmax. 512 threads (16 warps -> occ
// 25% at 1 CTA/SM). Grid (8, 64). Per CTA: 64 queries, 9 chunks of 64 keys.
// S-GEMM: outer-product f32x2 (row-pairs packed). O-GEMM: dot-style f32x2 --
// j contracted in pairs, even/odd partial sums in the two lanes, no dup movs,
// P kept untransposed (Ps[r][j], stride 66). Scores/P share one buffer.
// Softmax ignores the reference's log(fmask+1e-6) leakage (~1e-6 rel effect).
// ============================================================================
// smem (floats): Qs 16384 | KV 16384 | Ps 64*66=4224 | part 512 | misc 256
#define ATT_SMEM_FLOATS (16384 + 16384 + 4224 + 512 + 256)
#define ATT_SMEM_BYTES  (ATT_SMEM_FLOATS * 4)

__global__ __launch_bounds__(512, 1) void att_kernel(const float* __restrict__ mask)
{
    extern __shared__ float sm[];
    float* Qs   = sm;            // [c][r], stride 64
    float* KV   = sm + 16384;    // K then V, [c][j], stride 64
    float* Ps   = sm + 32768;    // scores then P, [r][j], stride 66
    float* part = sm + 36992;    // [8][64]
    float* m_s  = sm + 37504;
    float* l_s  = m_s + 64;
    float* sc_s = l_s + 64;
    float* msk  = sc_s + 64;

    const int n  = blockIdx.y;
    const int q0 = blockIdx.x * QT;
    const int Q0 = n * BLK + q0;
    const int tid  = threadIdx.x;
    const int tx   = tid & 31;   // S-GEMM cols tx*2
    const int ty   = tid >> 5;   // S-GEMM rows ty*4 (warp-uniform)
    const int cgrp = tid >> 4;   // O-GEMM channels cgrp*8..+7
    const int rgrp = tid & 15;   // O-GEMM rows rgrp*4..+3

    for (int i = tid; i < CDIM * QT; i += 512) {
        int c = i >> 6, r = i & 63;
        Qs[c * 64 + r] = g_q[(size_t)c * LSEQ + Q0 + r];
    }
    if (tid < 64) { m_s[tid] = -INFINITY; l_s[tid] = 0.f; }

    u64 acc2[8][4];              // [ci][row]: lanes = even/odd-j partial sums
#pragma unroll
    for (int i = 0; i < 8; i++)
#pragma unroll
        for (int j = 0; j < 4; j++) acc2[i][j] = 0ull;
    __syncthreads();

    const float escale = 0.0625f;  // 1/sqrt(256)

    for (int ch = 0; ch < 9; ch++) {
        const int c0 = q0 + ch * 64;            // window col base
        const int kbase = n * BLK - HALF + c0;  // global key pos of j=0

        // ---- load K chunk + mask chunk ----
        for (int i = tid; i < CDIM * 64; i += 512) {
            int c = i >> 6, j = i & 63;
            int kp = kbase + j;
            int kpc = min(max(kp, 0), LSEQ - 1);
            KV[c * 64 + j] = g_k[(size_t)c * LSEQ + kpc];
        }
        if (tid < 64) {
            int kp = kbase + tid;
            msk[tid] = (kp >= 0 && kp < LSEQ) ? mask[kp] : 0.f;
        }
        __syncthreads();

        // ---- S = scale * Q^T K (4 rows x 2 cols per thread), masked ----
        u64 s2[2][2];
#pragma unroll
        for (int p = 0; p < 2; p++)
#pragma unroll
            for (int j = 0; j < 2; j++) s2[p][j] = 0ull;
#pragma unroll 8
        for (int c = 0; c < CDIM; c++) {
            float4 a = *(const float4*)&Qs[c * 64 + ty * 4];
            float2 b = *(const float2*)&KV[c * 64 + tx * 2];
            u64 ra0 = pk2(a.x, a.y), ra1 = pk2(a.z, a.w);
            u64 rb0 = dup2(b.x), rb1 = dup2(b.y);
            fma2(s2[0][0], ra0, rb0); fma2(s2[0][1], ra0, rb1);
            fma2(s2[1][0], ra1, rb0); fma2(s2[1][1], ra1, rb1);
        }
#pragma unroll
        for (int p = 0; p < 2; p++)
#pragma unroll
            for (int jc = 0; jc < 2; jc++) {
                float2 v = up2(s2[p][jc]);
                int jj = tx * 2 + jc;
                int wcol = c0 + jj;
                float mk = msk[jj];
                int r0 = ty * 4 + 2 * p;
                bool v0 = (wcol >= q0 + r0) && (wcol < q0 + r0 + BLK) && (mk > 0.f);
                bool v1 = (wcol >= q0 + r0 + 1) && (wcol < q0 + r0 + 1 + BLK) && (mk > 0.f);
                Ps[r0 * 66 + jj]       = v0 ? v.x * escale : -INFINITY;
                Ps[(r0 + 1) * 66 + jj] = v1 ? v.y * escale : -INFINITY;
            }
        __syncthreads();

        // ---- load V chunk (overwrites K) + row-max partials ----
        for (int i = tid; i < CDIM * 64; i += 512) {
            int c = i >> 6, j = i & 63;
            int kp = kbase + j;
            int kpc = min(max(kp, 0), LSEQ - 1);
            KV[c * 64 + j] = g_v[(size_t)c * LSEQ + kpc];
        }
        {
            int r = tid & 63, qq = tid >> 6;
            float mx = -INFINITY;
#pragma unroll
            for (int k = 0; k < 8; k++)
                mx = fmaxf(mx, Ps[r * 66 + qq * 8 + k]);
            part[qq * 64 + r] = mx;
        }
        __syncthreads();

        // ---- online softmax stats ----
        if (tid < 64) {
            float m_old = m_s[tid];
            float mx = -INFINITY;
#pragma unroll
            for (int k = 0; k < 8; k++) mx = fmaxf(mx, part[k * 64 + tid]);
            float m_new = fmaxf(m_old, mx);
            float sc = (m_new > -1e30f) ? __expf(m_old - m_new) : 1.0f;
            m_s[tid] = m_new;
            sc_s[tid] = sc;
            l_s[tid] *= sc;
        }
        __syncthreads();

        // ---- P = exp(S - m) in place, row-sum partials ----
        {
            int r = tid & 63, qq = tid >> 6;
            float mrow = m_s[r];
            float ps = 0.f;
#pragma unroll
            for (int k = 0; k < 8; k++) {
                int j = qq * 8 + k;
                float s = Ps[r * 66 + j];
                float p = (s > -1e30f) ? __expf(s - mrow) : 0.f;
                Ps[r * 66 + j] = p;
                ps += p;
            }
            part[qq * 64 + r] = ps;
        }
        __syncthreads();

        if (tid < 64) {
            float s = 0.f;
#pragma unroll
            for (int k = 0; k < 8; k++) s += part[k * 64 + tid];
            l_s[tid] += s;
        }

        // ---- O accumulate (dot-style): rescale, then j-pairs ----
#pragma unroll
        for (int r = 0; r < 4; r++) {
            u64 sc = dup2(sc_s[rgrp * 4 + r]);
#pragma unroll
            for (int ci = 0; ci < 8; ci++) mul2(acc2[ci][r], sc);
        }
#pragma unroll 2
        for (int jp = 0; jp < 64; jp += 2) {
            u64 P2[4], V2[8];
#pragma unroll
            for (int r = 0; r < 4; r++) {
                float2 p = *(const float2*)&Ps[(rgrp * 4 + r) * 66 + jp];
                P2[r] = pk2(p.x, p.y);
            }
#pragma unroll
            for (int ci = 0; ci < 8; ci++) {
                float2 v = *(const float2*)&KV[(cgrp * 8 + ci) * 64 + jp];
                V2[ci] = pk2(v.x, v.y);
            }
#pragma unroll
            for (int ci = 0; ci < 8; ci++)
#pragma unroll
                for (int r = 0; r < 4; r++) fma2(acc2[ci][r], V2[ci], P2[r]);
        }
        __syncthreads();
    }

    // ---- epilogue: combine even/odd lanes, normalize, relu, store ----
#pragma unroll
    for (int r = 0; r < 4; r++) {
        int row = rgrp * 4 + r;
        float l = l_s[row];
        float inv = (l > 0.f) ? 1.0f / l : 0.f;
#pragma unroll
        for (int ci = 0; ci < 8; ci++) {
            float2 h = up2(acc2[ci][r]);
            float v = (h.x + h.y) * inv;
            g_att[(size_t)(cgrp * 8 + ci) * LSEQ + Q0 + row] = fmaxf(v, 0.f);
        }
    }
}

// ============================================================================
extern "C" void kernel_launch(void* const* d_in, const int* in_sizes, int n_in,
                              void* d_out, int out_size)
{
    (void)in_sizes; (void)n_in; (void)out_size;
    const float* x1   = (const float*)d_in[0];
    // d_in[1] = x2 (unused by reference)
    const float* mask = (const float*)d_in[2];
    const float* Wq = (const float*)d_in[3];
    const float* bq = (const float*)d_in[4];
    const float* Wk = (const float*)d_in[5];
    const float* bk = (const float*)d_in[6];
    const float* Wv = (const float*)d_in[7];
    const float* bv = (const float*)d_in[8];
    const float* Wo = (const float*)d_in[9];
    const float* bo = (const float*)d_in[10];
    float* out = (float*)d_out;

    float *pq, *pk, *pv, *patt;
    cudaGetSymbolAddress((void**)&pq,  g_q);
    cudaGetSymbolAddress((void**)&pk,  g_k);
    cudaGetSymbolAddress((void**)&pv,  g_v);
    cudaGetSymbolAddress((void**)&patt, g_att);

    cudaFuncSetAttribute(att_kernel,
                         cudaFuncAttributeMaxDynamicSharedMemorySize, ATT_SMEM_BYTES);

    // QKV projections: M=256, K=512
    dim3 g1(LSEQ / 128, CDIM / 128);
    gemm_kernel<<<g1, 256>>>(Wq, x1, bq, pq, QDIM, nullptr);
    gemm_kernel<<<g1, 256>>>(Wk, x1, bk, pk, QDIM, nullptr);
    gemm_kernel<<<g1, 256>>>(Wv, x1, bv, pv, QDIM, nullptr);

    // Sliding-window attention (+ relu), writes g_att
    dim3 ga(BLK / QT, LSEQ / BLK);
    att_kernel<<<ga, 512, ATT_SMEM_BYTES>>>(mask);

    // Output projection: M=512, K=256, fused bias + final mask multiply
    dim3 g2(LSEQ / 128, QDIM / 128);
    gemm_kernel<<<g2, 256>>>(Wo, patt, bo, out, CDIM, mask);
}

// round 10
// speedup vs baseline: 1.4897x; 1.4897x over previous
#include <cuda_runtime.h>
#include <math.h>
#include <stdint.h>

#define LSEQ  32768
#define CDIM  256      // projected channels
#define QDIM  512      // input/output channels
#define BLK   512      // attention block length
#define HALF  256
#define QT    64       // query tile per CTA

typedef unsigned long long u64;

// ---- packed f32x2 helpers (sm_100+; ptxas never auto-generates FFMA2) ----
__device__ __forceinline__ u64 pk2(float lo, float hi) {
    u64 r;
    asm("mov.b64 %0, {%1, %2};" : "=l"(r)
        : "r"(__float_as_uint(lo)), "r"(__float_as_uint(hi)));
    return r;
}
__device__ __forceinline__ u64 dup2(float v) { return pk2(v, v); }
__device__ __forceinline__ void fma2(u64 &d, u64 a, u64 b) {
    asm("fma.rn.f32x2 %0, %1, %2, %0;" : "+l"(d) : "l"(a), "l"(b));
}
__device__ __forceinline__ void mul2(u64 &d, u64 a) {
    asm("mul.rn.f32x2 %0, %0, %1;" : "+l"(d) : "l"(a));
}
__device__ __forceinline__ float2 up2(u64 v) {
    float2 f;
    unsigned lo, hi;
    asm("mov.b64 {%0, %1}, %2;" : "=r"(lo), "=r"(hi) : "l"(v));
    f.x = __uint_as_float(lo); f.y = __uint_as_float(hi);
    return f;
}

// ---- scratch (static device globals; runtime alloc is forbidden) ----
__device__ float g_q[(size_t)CDIM * LSEQ];
__device__ float g_k[(size_t)CDIM * LSEQ];
__device__ float g_v[(size_t)CDIM * LSEQ];
__device__ float g_att[(size_t)CDIM * LSEQ];

// ============================================================================
// GEMM: out[m][l] = bias[m] + sum_k W[m][k] * X[k][l]   (optionally * mm[l])
// Measured-good layout (round-5 2068us config): tile 128x128, BK=16, 256 thr,
// 8x8 microtile, f32x2 accumulators with rows paired, cols split
// {tx*4, 64+tx*4}. Added: register prefetch of the next K-tile. NO min-blocks
// occupancy cap (the round-9 (256,2) cap caused spills -> 2x GEMM regression).
// ============================================================================
__global__ __launch_bounds__(256) void gemm_kernel(
    const float* __restrict__ W, const float* __restrict__ X,
    const float* __restrict__ bias, float* __restrict__ outp,
    int K, const float* __restrict__ mm)
{
    __shared__ float Ws[16][128];
    __shared__ float Xs[16][128];

    const int n0 = blockIdx.x * 128;
    const int m0 = blockIdx.y * 128;
    const int tid = threadIdx.x;
    const int tx = tid & 15;    // cols tx*4 .. +3  and  64+tx*4 .. +3
    const int ty = tid >> 4;    // rows ty*8 .. +7

    // per-thread load coordinates (fixed across tiles)
    const int wm = tid >> 4,  wk = tid & 15;    // W: 8 rows, stride 16 in m
    const int xk = tid >> 7,  xn = tid & 127;   // X: 8 k-rows, stride 2 in k

    u64 acc2[4][8];             // [row-pair][col]: rows (ty*8+2i, ty*8+2i+1)
#pragma unroll
    for (int i = 0; i < 4; i++)
#pragma unroll
        for (int j = 0; j < 8; j++) acc2[i][j] = 0ull;

    float wreg[8], xreg[8];

    // prefetch tile 0
#pragma unroll
    for (int i = 0; i < 8; i++)
        wreg[i] = W[(size_t)(m0 + wm + 16 * i) * K + wk];
#pragma unroll
    for (int i = 0; i < 8; i++)
        xreg[i] = X[(size_t)(xk + 2 * i) * LSEQ + n0 + xn];

    for (int k0 = 0; k0 < K; k0 += 16) {
        // commit prefetched tile to smem
#pragma unroll
        for (int i = 0; i < 8; i++) Ws[wk][wm + 16 * i] = wreg[i];
#pragma unroll
        for (int i = 0; i < 8; i++) Xs[xk + 2 * i][xn] = xreg[i];
        __syncthreads();

        // prefetch next tile while computing this one
        if (k0 + 16 < K) {
#pragma unroll
            for (int i = 0; i < 8; i++)
                wreg[i] = W[(size_t)(m0 + wm + 16 * i) * K + k0 + 16 + wk];
#pragma unroll
            for (int i = 0; i < 8; i++)
                xreg[i] = X[(size_t)(k0 + 16 + xk + 2 * i) * LSEQ + n0 + xn];
        }

#pragma unroll
        for (int kk = 0; kk < 16; kk++) {
            float4 a0 = *(const float4*)&Ws[kk][ty * 8];
            float4 a1 = *(const float4*)&Ws[kk][ty * 8 + 4];
            u64 ra[4] = {pk2(a0.x, a0.y), pk2(a0.z, a0.w),
                         pk2(a1.x, a1.y), pk2(a1.z, a1.w)};
            float4 b0 = *(const float4*)&Xs[kk][tx * 4];
            float4 b1 = *(const float4*)&Xs[kk][64 + tx * 4];
            u64 rb[8] = {dup2(b0.x), dup2(b0.y), dup2(b0.z), dup2(b0.w),
                         dup2(b1.x), dup2(b1.y), dup2(b1.z), dup2(b1.w)};
#pragma unroll
            for (int i = 0; i < 4; i++)
#pragma unroll
                for (int j = 0; j < 8; j++) fma2(acc2[i][j], ra[i], rb[j]);
        }
        __syncthreads();
    }

    // epilogue: bias, optional mask, float4 stores
    float mv[8];
#pragma unroll
    for (int j = 0; j < 4; j++) {
        mv[j]     = mm ? mm[n0 + tx * 4 + j]      : 1.f;
        mv[4 + j] = mm ? mm[n0 + 64 + tx * 4 + j] : 1.f;
    }
#pragma unroll
    for (int i = 0; i < 4; i++) {
        int r0 = m0 + ty * 8 + 2 * i;
        int r1 = r0 + 1;
        float bb0 = bias[r0], bb1 = bias[r1];
        float v0[8], v1[8];
#pragma unroll
        for (int j = 0; j < 8; j++) {
            float2 p = up2(acc2[i][j]);
            v0[j] = (p.x + bb0) * mv[j];
            v1[j] = (p.y + bb1) * mv[j];
        }
        *(float4*)&outp[(size_t)r0 * LSEQ + n0 + tx * 4]      = make_float4(v0[0], v0[1], v0[2], v0[3]);
        *(float4*)&outp[(size_t)r0 * LSEQ + n0 + 64 + tx * 4] = make_float4(v0[4], v0[5], v0[6], v0[7]);
        *(float4*)&outp[(size_t)r1 * LSEQ + n0 + tx * 4]      = make_float4(v1[0], v1[1], v1[2], v1[3]);
        *(float4*)&outp[(size_t)r1 * LSEQ + n0 + 64 + tx * 4] = make_float4(v1[4], v1[5], v1[6], v1[7]);
    }
}

// ============================================================================
// Sliding-window attention with online softmax. 512 threads, grid (8, 64).
// O-GEMM rows per thread remapped to {rgrp, rgrp+16, rgrp+32, rgrp+48}:
// consecutive lanes read Ps rows at stride 66 floats (== 2 words mod 32) ->
// conflict-free LDS.64 (was 4-way conflicted with the rgrp*4+r mapping).
// Softmax ignores the reference's log(fmask+1e-6) leakage (~1e-6 rel effect).
// ============================================================================
// smem (floats): Qs 16384 | KV 16384 | Ps 64*66=4224 | part 512 | misc 256
#define ATT_SMEM_FLOATS (16384 + 16384 + 4224 + 512 + 256)
#define ATT_SMEM_BYTES  (ATT_SMEM_FLOATS * 4)

__global__ __launch_bounds__(512, 1) void att_kernel(const float* __restrict__ mask)
{
    extern __shared__ float sm[];
    float* Qs   = sm;            // [c][r], stride 64
    float* KV   = sm + 16384;    // K then V, [c][j], stride 64
    float* Ps   = sm + 32768;    // scores then P, [r][j], stride 66
    float* part = sm + 36992;    // [8][64]
    float* m_s  = sm + 37504;
    float* l_s  = m_s + 64;
    float* sc_s = l_s + 64;
    float* msk  = sc_s + 64;

    const int n  = blockIdx.y;
    const int q0 = blockIdx.x * QT;
    const int Q0 = n * BLK + q0;
    const int tid  = threadIdx.x;
    const int tx   = tid & 31;   // S-GEMM cols tx*2
    const int ty   = tid >> 5;   // S-GEMM rows ty*4 (warp-uniform)
    const int cgrp = tid >> 4;   // O-GEMM channels cgrp*8..+7
    const int rgrp = tid & 15;   // O-GEMM rows rgrp + 16*r (interleaved)

    for (int i = tid; i < CDIM * QT; i += 512) {
        int c = i >> 6, r = i & 63;
        Qs[c * 64 + r] = g_q[(size_t)c * LSEQ + Q0 + r];
    }
    if (tid < 64) { m_s[tid] = -INFINITY; l_s[tid] = 0.f; }

    u64 acc2[8][4];              // [ci][r]: lanes = even/odd-j partial sums
#pragma unroll
    for (int i = 0; i < 8; i++)
#pragma unroll
        for (int j = 0; j < 4; j++) acc2[i][j] = 0ull;
    __syncthreads();

    const float escale = 0.0625f;  // 1/sqrt(256)

    for (int ch = 0; ch < 9; ch++) {
        const int c0 = q0 + ch * 64;            // window col base
        const int kbase = n * BLK - HALF + c0;  // global key pos of j=0

        // ---- load K chunk + mask chunk ----
        for (int i = tid; i < CDIM * 64; i += 512) {
            int c = i >> 6, j = i & 63;
            int kp = kbase + j;
            int kpc = min(max(kp, 0), LSEQ - 1);
            KV[c * 64 + j] = g_k[(size_t)c * LSEQ + kpc];
        }
        if (tid < 64) {
            int kp = kbase + tid;
            msk[tid] = (kp >= 0 && kp < LSEQ) ? mask[kp] : 0.f;
        }
        __syncthreads();

        // ---- S = scale * Q^T K (4 rows x 2 cols per thread), masked ----
        u64 s2[2][2];
#pragma unroll
        for (int p = 0; p < 2; p++)
#pragma unroll
            for (int j = 0; j < 2; j++) s2[p][j] = 0ull;
#pragma unroll 8
        for (int c = 0; c < CDIM; c++) {
            float4 a = *(const float4*)&Qs[c * 64 + ty * 4];
            float2 b = *(const float2*)&KV[c * 64 + tx * 2];
            u64 ra0 = pk2(a.x, a.y), ra1 = pk2(a.z, a.w);
            u64 rb0 = dup2(b.x), rb1 = dup2(b.y);
            fma2(s2[0][0], ra0, rb0); fma2(s2[0][1], ra0, rb1);
            fma2(s2[1][0], ra1, rb0); fma2(s2[1][1], ra1, rb1);
        }
#pragma unroll
        for (int p = 0; p < 2; p++)
#pragma unroll
            for (int jc = 0; jc < 2; jc++) {
                float2 v = up2(s2[p][jc]);
                int jj = tx * 2 + jc;
                int wcol = c0 + jj;
                float mk = msk[jj];
                int r0 = ty * 4 + 2 * p;
                bool v0 = (wcol >= q0 + r0) && (wcol < q0 + r0 + BLK) && (mk > 0.f);
                bool v1 = (wcol >= q0 + r0 + 1) && (wcol < q0 + r0 + 1 + BLK) && (mk > 0.f);
                Ps[r0 * 66 + jj]       = v0 ? v.x * escale : -INFINITY;
                Ps[(r0 + 1) * 66 + jj] = v1 ? v.y * escale : -INFINITY;
            }
        __syncthreads();

        // ---- load V chunk (overwrites K) + row-max partials ----
        for (int i = tid; i < CDIM * 64; i += 512) {
            int c = i >> 6, j = i & 63;
            int kp = kbase + j;
            int kpc = min(max(kp, 0), LSEQ - 1);
            KV[c * 64 + j] = g_v[(size_t)c * LSEQ + kpc];
        }
        {
            int r = tid & 63, qq = tid >> 6;
            float mx = -INFINITY;
#pragma unroll
            for (int k = 0; k < 8; k++)
                mx = fmaxf(mx, Ps[r * 66 + qq * 8 + k]);
            part[qq * 64 + r] = mx;
        }
        __syncthreads();

        // ---- online softmax stats ----
        if (tid < 64) {
            float m_old = m_s[tid];
            float mx = -INFINITY;
#pragma unroll
            for (int k = 0; k < 8; k++) mx = fmaxf(mx, part[k * 64 + tid]);
            float m_new = fmaxf(m_old, mx);
            float sc = (m_new > -1e30f) ? __expf(m_old - m_new) : 1.0f;
            m_s[tid] = m_new;
            sc_s[tid] = sc;
            l_s[tid] *= sc;
        }
        __syncthreads();

        // ---- P = exp(S - m) in place, row-sum partials ----
        {
            int r = tid & 63, qq = tid >> 6;
            float mrow = m_s[r];
            float ps = 0.f;
#pragma unroll
            for (int k = 0; k < 8; k++) {
                int j = qq * 8 + k;
                float s = Ps[r * 66 + j];
                float p = (s > -1e30f) ? __expf(s - mrow) : 0.f;
                Ps[r * 66 + j] = p;
                ps += p;
            }
            part[qq * 64 + r] = ps;
        }
        __syncthreads();

        if (tid < 64) {
            float s = 0.f;
#pragma unroll
            for (int k = 0; k < 8; k++) s += part[k * 64 + tid];
            l_s[tid] += s;
        }

        // ---- O accumulate (dot-style, conflict-free rows): rescale, j-pairs ----
#pragma unroll
        for (int r = 0; r < 4; r++) {
            u64 sc = dup2(sc_s[rgrp + 16 * r]);
#pragma unroll
            for (int ci = 0; ci < 8; ci++) mul2(acc2[ci][r], sc);
        }
#pragma unroll 2
        for (int jp = 0; jp < 64; jp += 2) {
            u64 P2[4], V2[8];
#pragma unroll
            for (int r = 0; r < 4; r++) {
                float2 p = *(const float2*)&Ps[(rgrp + 16 * r) * 66 + jp];
                P2[r] = pk2(p.x, p.y);
            }
#pragma unroll
            for (int ci = 0; ci < 8; ci++) {
                float2 v = *(const float2*)&KV[(cgrp * 8 + ci) * 64 + jp];
                V2[ci] = pk2(v.x, v.y);
            }
#pragma unroll
            for (int ci = 0; ci < 8; ci++)
#pragma unroll
                for (int r = 0; r < 4; r++) fma2(acc2[ci][r], V2[ci], P2[r]);
        }
        __syncthreads();
    }

    // ---- epilogue: combine even/odd lanes, normalize, relu, store ----
#pragma unroll
    for (int r = 0; r < 4; r++) {
        int row = rgrp + 16 * r;
        float l = l_s[row];
        float inv = (l > 0.f) ? 1.0f / l : 0.f;
#pragma unroll
        for (int ci = 0; ci < 8; ci++) {
            float2 h = up2(acc2[ci][r]);
            float v = (h.x + h.y) * inv;
            g_att[(size_t)(cgrp * 8 + ci) * LSEQ + Q0 + row] = fmaxf(v, 0.f);
        }
    }
}

// ============================================================================
extern "C" void kernel_launch(void* const* d_in, const int* in_sizes, int n_in,
                              void* d_out, int out_size)
{
    (void)in_sizes; (void)n_in; (void)out_size;
    const float* x1   = (const float*)d_in[0];
    // d_in[1] = x2 (unused by reference)
    const float* mask = (const float*)d_in[2];
    const float* Wq = (const float*)d_in[3];
    const float* bq = (const float*)d_in[4];
    const float* Wk = (const float*)d_in[5];
    const float* bk = (const float*)d_in[6];
    const float* Wv = (const float*)d_in[7];
    const float* bv = (const float*)d_in[8];
    const float* Wo = (const float*)d_in[9];
    const float* bo = (const float*)d_in[10];
    float* out = (float*)d_out;

    float *pq, *pk, *pv, *patt;
    cudaGetSymbolAddress((void**)&pq,  g_q);
    cudaGetSymbolAddress((void**)&pk,  g_k);
    cudaGetSymbolAddress((void**)&pv,  g_v);
    cudaGetSymbolAddress((void**)&patt, g_att);

    cudaFuncSetAttribute(att_kernel,
                         cudaFuncAttributeMaxDynamicSharedMemorySize, ATT_SMEM_BYTES);

    // QKV projections: M=256, K=512
    dim3 g1(LSEQ / 128, CDIM / 128);
    gemm_kernel<<<g1, 256>>>(Wq, x1, bq, pq, QDIM, nullptr);
    gemm_kernel<<<g1, 256>>>(Wk, x1, bk, pk, QDIM, nullptr);
    gemm_kernel<<<g1, 256>>>(Wv, x1, bv, pv, QDIM, nullptr);

    // Sliding-window attention (+ relu), writes g_att
    dim3 ga(BLK / QT, LSEQ / BLK);
    att_kernel<<<ga, 512, ATT_SMEM_BYTES>>>(mask);

    // Output projection: M=512, K=256, fused bias + final mask multiply
    dim3 g2(LSEQ / 128, QDIM / 128);
    gemm_kernel<<<g2, 256>>>(Wo, patt, bo, out, CDIM, mask);
}